// round 4
// baseline (speedup 1.0000x reference)
#include <cuda_runtime.h>
#include <cstdint>
#include <cfloat>

// Problem constants
#define BB 32
#define KK 5
#define TT 12
#define VV 50257
#define HH 512
#define NBEAMS (BB*KK)           // 160
#define NCAND (KK*VV)            // 251285
#define NPART 8                  // partial-topk blocks per batch row

// Output layout: ONE f32 buffer, outputs cast to f32, concatenated in
// reference return order (element offsets).
#define OFF_SEQ   ((size_t)0)                         // 32*5*13 = 2080
#define OFF_BSLP  ((size_t)2080)                      // 32*5*13*50257
#define OFF_SUM   (OFF_BSLP + (size_t)BB*KK*13*VV)    // 160
#define OFF_STATE (OFF_SUM + (size_t)NBEAMS)          // 2*160*512

// Scratch (static device globals; no allocation)
__device__ float g_part_val[BB * NPART * 5];
__device__ int   g_part_idx[BB * NPART * 5];
__device__ int   g_beam_ix[NBEAMS];

__device__ __forceinline__ bool better(float va, int ia, float vb, int ib) {
    return (va > vb) || (va == vb && ia < ib);
}

// ---------------------------------------------------------------------------
// Kernel 1: partial top-5 per (batch row, partition). grid (NPART, BB), 256 thr
// ---------------------------------------------------------------------------
__global__ __launch_bounds__(256) void topk_partial_kernel(
    const float* __restrict__ logprobs,   // (160, V)
    const float* __restrict__ bsum)       // (32, 5)
{
    const int b    = blockIdx.y;
    const int part = blockIdx.x;
    const int per  = (NCAND + NPART - 1) / NPART;
    const int start = part * per;
    const int end   = min(start + per, NCAND);

    float bs[KK];
#pragma unroll
    for (int k = 0; k < KK; k++) bs[k] = bsum[b * KK + k];

    float tv[5]; int ti[5];
#pragma unroll
    for (int j = 0; j < 5; j++) { tv[j] = -FLT_MAX; ti[j] = 0x7FFFFFFF; }

    const float* lpb = logprobs + (size_t)b * KK * VV;
    for (int i = start + threadIdx.x; i < end; i += blockDim.x) {
        int k = i / VV;
        int v = i - k * VV;
        float val = bs[k] + lpb[(size_t)k * VV + v];
        if (better(val, i, tv[4], ti[4])) {
            tv[4] = val; ti[4] = i;
#pragma unroll
            for (int j = 4; j > 0; j--) {
                if (better(tv[j], ti[j], tv[j-1], ti[j-1])) {
                    float fv = tv[j]; tv[j] = tv[j-1]; tv[j-1] = fv;
                    int   iv = ti[j]; ti[j] = ti[j-1]; ti[j-1] = iv;
                }
            }
        }
    }

    __shared__ float sv[256 * 5];
    __shared__ int   si[256 * 5];
    const int tid = threadIdx.x;
#pragma unroll
    for (int j = 0; j < 5; j++) { sv[tid*5+j] = tv[j]; si[tid*5+j] = ti[j]; }
    __syncthreads();

    for (int s = blockDim.x / 2; s > 0; s >>= 1) {
        if (tid < s) {
            // merge sorted 5-lists at tid and tid+s -> tid
            float mv[5]; int mi[5];
            int pa = 0, pb = 0;
            const int A = tid * 5, Bo = (tid + s) * 5;
#pragma unroll
            for (int j = 0; j < 5; j++) {
                if (better(sv[A+pa], si[A+pa], sv[Bo+pb], si[Bo+pb])) {
                    mv[j] = sv[A+pa]; mi[j] = si[A+pa]; pa++;
                } else {
                    mv[j] = sv[Bo+pb]; mi[j] = si[Bo+pb]; pb++;
                }
            }
#pragma unroll
            for (int j = 0; j < 5; j++) { sv[A+j] = mv[j]; si[A+j] = mi[j]; }
        }
        __syncthreads();
    }

    if (tid == 0) {
        const int base = (b * NPART + part) * 5;
#pragma unroll
        for (int j = 0; j < 5; j++) {
            g_part_val[base + j] = sv[j];
            g_part_idx[base + j] = si[j];
        }
    }
}

// ---------------------------------------------------------------------------
// Kernel 2: merge partials per batch row; emit beam_ix + small outputs
// (beam_seq_new, beam_logprobs_sum_new, both cast to f32). grid (BB), 1 thr.
// ---------------------------------------------------------------------------
__global__ void topk_merge_kernel(
    const int* __restrict__ beam_seq,  // (32,5,12) int32
    float* __restrict__ out)
{
    const int b = blockIdx.x;
    float tv[5]; int ti[5];
#pragma unroll
    for (int j = 0; j < 5; j++) { tv[j] = -FLT_MAX; ti[j] = 0x7FFFFFFF; }

    const int base = b * NPART * 5;
    for (int c = 0; c < NPART * 5; c++) {
        float val = g_part_val[base + c];
        int   idx = g_part_idx[base + c];
        if (better(val, idx, tv[4], ti[4])) {
            tv[4] = val; ti[4] = idx;
            for (int j = 4; j > 0; j--) {
                if (better(tv[j], ti[j], tv[j-1], ti[j-1])) {
                    float fv = tv[j]; tv[j] = tv[j-1]; tv[j-1] = fv;
                    int   iv = ti[j]; ti[j] = ti[j-1]; ti[j-1] = iv;
                } else break;
            }
        }
    }

#pragma unroll
    for (int j = 0; j < 5; j++) {
        int idx = ti[j];
        int bi  = idx / VV;
        int sel = idx - bi * VV;
        g_beam_ix[b * KK + j] = bi;
        // beam_logprobs_sum_new == ys (top-k candidate values)
        out[OFF_SUM + b * KK + j] = tv[j];
        // beam_seq_new (cast to f32): gathered int32 prefix + new token
        float* seq_out = out + OFF_SEQ + (size_t)(b * KK + j) * (TT + 1);
        const int* seq_src = beam_seq + (size_t)(b * KK + bi) * TT;
        for (int t = 0; t < TT; t++) seq_out[t] = (float)seq_src[t];
        seq_out[TT] = (float)sel;
    }
}

// ---------------------------------------------------------------------------
// Kernel 3: big gather-concat for beam_seq_logprobs_new (f32).
// grid (ceil(V/1024), 2080), 256 thr, 4 elems/thr. HBM-bound.
// ---------------------------------------------------------------------------
__global__ __launch_bounds__(256) void gather_bslp_kernel(
    const float* __restrict__ bslp,    // (32,5,12,V)
    const float* __restrict__ unaug,   // (160,V)
    float* __restrict__ out)
{
    const int row = blockIdx.y;            // 0..2079 = (b*K+k)*13 + t
    const int t   = row % (TT + 1);
    const int bk  = row / (TT + 1);
    const int b   = bk / KK;
    const int bi  = g_beam_ix[bk];

    const float* src;
    if (t < TT) src = bslp + (((size_t)(b * KK + bi) * TT + t) * VV);
    else        src = unaug + (size_t)(b * KK + bi) * VV;
    float* dst = out + OFF_BSLP + (size_t)row * VV;

    const int base = blockIdx.x * (blockDim.x * 4);
#pragma unroll
    for (int u = 0; u < 4; u++) {
        int v = base + u * blockDim.x + threadIdx.x;
        if (v < VV) dst[v] = src[v];
    }
}

// ---------------------------------------------------------------------------
// Kernel 4: state gather (f32). 2*160*512 = 163840 elems.
// ---------------------------------------------------------------------------
__global__ __launch_bounds__(256) void state_kernel(
    const float* __restrict__ state,   // (2,160,512)
    float* __restrict__ out)
{
    int idx = blockIdx.x * blockDim.x + threadIdx.x;
    const int TOT = 2 * NBEAMS * HH;
    if (idx >= TOT) return;
    int s = idx / (NBEAMS * HH);
    int r = idx - s * (NBEAMS * HH);
    int j = r / HH;            // b*K + k
    int h = r - j * HH;
    int b = j / KK;
    int bi = g_beam_ix[j];
    out[OFF_STATE + idx] = state[(size_t)s * NBEAMS * HH + (size_t)(b * KK + bi) * HH + h];
}

// ---------------------------------------------------------------------------
extern "C" void kernel_launch(void* const* d_in, const int* in_sizes, int n_in,
                              void* d_out, int out_size) {
    const float* logprobs = (const float*)d_in[0];       // (160, V)
    const float* unaug    = (const float*)d_in[1];       // (160, V)
    const int*   beam_seq = (const int*)d_in[2];         // (32,5,12) int32
    const float* bslp     = (const float*)d_in[3];       // (32,5,12,V)
    const float* bsum     = (const float*)d_in[4];       // (32,5)
    const float* state    = (const float*)d_in[5];       // (2,160,512)
    // d_in[6] = bdash (=5), hardcoded

    float* out = (float*)d_out;

    {
        dim3 grid(NPART, BB);
        topk_partial_kernel<<<grid, 256>>>(logprobs, bsum);
    }
    topk_merge_kernel<<<BB, 1>>>(beam_seq, out);
    {
        dim3 grid((VV + 1023) / 1024, BB * KK * (TT + 1));  // (50, 2080)
        gather_bslp_kernel<<<grid, 256>>>(bslp, unaug, out);
    }
    {
        const int TOT = 2 * NBEAMS * HH;
        state_kernel<<<(TOT + 255) / 256, 256>>>(state, out);
    }
}

// round 5
// speedup vs baseline: 1.1111x; 1.1111x over previous
#include <cuda_runtime.h>
#include <cstdint>
#include <cfloat>

// Problem constants
#define BB 32
#define KK 5
#define TT 12
#define VV 50257
#define HH 512
#define NBEAMS (BB*KK)           // 160
#define NPART 8                  // partial-topk blocks per batch row
#define PERV ((VV + NPART - 1) / NPART)   // 6283

// Output layout: ONE f32 buffer, outputs cast to f32, concatenated in
// reference return order (element offsets). Verified R3: rel_err == 0.
#define OFF_SEQ   ((size_t)0)                         // 32*5*13 = 2080
#define OFF_BSLP  ((size_t)2080)
#define OFF_SUM   (OFF_BSLP + (size_t)BB*KK*13*VV)    // 104536640
#define OFF_STATE (OFF_SUM + (size_t)NBEAMS)          // 104536800 (mod 4 == 0)

#define NROWS_BSLP (BB*KK*(TT+1))   // 2080
#define NROWS_STATE (2*NBEAMS)      // 320

// Scratch (static device globals; no allocation)
__device__ float g_part_val[BB * NPART * 5];
__device__ int   g_part_idx[BB * NPART * 5];
__device__ int   g_beam_ix[NBEAMS];

__device__ __forceinline__ bool better(float va, int ia, float vb, int ib) {
    return (va > vb) || (va == vb && ia < ib);
}

// ---------------------------------------------------------------------------
// Kernel 1: partial top-5 per (batch row, v-partition). grid (NPART, BB).
// k-outer / v-inner loop: no per-element division.
// ---------------------------------------------------------------------------
__global__ __launch_bounds__(256) void topk_partial_kernel(
    const float* __restrict__ logprobs,   // (160, V)
    const float* __restrict__ bsum)       // (32, 5)
{
    const int b       = blockIdx.y;
    const int part    = blockIdx.x;
    const int v_start = part * PERV;
    const int v_end   = min(v_start + PERV, VV);
    const int tid     = threadIdx.x;

    float tv[5]; int ti[5];
#pragma unroll
    for (int j = 0; j < 5; j++) { tv[j] = -FLT_MAX; ti[j] = 0x7FFFFFFF; }

    const float* lpb = logprobs + (size_t)b * KK * VV;
#pragma unroll
    for (int k = 0; k < KK; k++) {
        const float bsk = bsum[b * KK + k];
        const float* p  = lpb + (size_t)k * VV;
        const int kbase = k * VV;
        for (int v = v_start + tid; v < v_end; v += 256) {
            float val = bsk + p[v];
            int   idx = kbase + v;
            if (better(val, idx, tv[4], ti[4])) {
                tv[4] = val; ti[4] = idx;
#pragma unroll
                for (int j = 4; j > 0; j--) {
                    if (better(tv[j], ti[j], tv[j-1], ti[j-1])) {
                        float fv = tv[j]; tv[j] = tv[j-1]; tv[j-1] = fv;
                        int   iv = ti[j]; ti[j] = ti[j-1]; ti[j-1] = iv;
                    }
                }
            }
        }
    }

    __shared__ float sv[256 * 5];
    __shared__ int   si[256 * 5];
#pragma unroll
    for (int j = 0; j < 5; j++) { sv[tid*5+j] = tv[j]; si[tid*5+j] = ti[j]; }
    __syncthreads();

    for (int s = 128; s > 0; s >>= 1) {
        if (tid < s) {
            float mv[5]; int mi[5];
            int pa = 0, pb = 0;
            const int A = tid * 5, Bo = (tid + s) * 5;
#pragma unroll
            for (int j = 0; j < 5; j++) {
                if (better(sv[A+pa], si[A+pa], sv[Bo+pb], si[Bo+pb])) {
                    mv[j] = sv[A+pa]; mi[j] = si[A+pa]; pa++;
                } else {
                    mv[j] = sv[Bo+pb]; mi[j] = si[Bo+pb]; pb++;
                }
            }
#pragma unroll
            for (int j = 0; j < 5; j++) { sv[A+j] = mv[j]; si[A+j] = mi[j]; }
        }
        __syncthreads();
    }

    if (tid == 0) {
        const int base = (b * NPART + part) * 5;
#pragma unroll
        for (int j = 0; j < 5; j++) {
            g_part_val[base + j] = sv[j];
            g_part_idx[base + j] = si[j];
        }
    }
}

// ---------------------------------------------------------------------------
// Kernel 2: warp-parallel merge of 40 partials per batch row.
// grid (BB), 32 threads. 5 rounds of warp argmax (with index tiebreak),
// then warp-parallel beam_seq gather/concat.
// ---------------------------------------------------------------------------
__global__ __launch_bounds__(32) void topk_merge_kernel(
    const int* __restrict__ beam_seq,  // (32,5,12) int32
    float* __restrict__ out)
{
    const int b    = blockIdx.x;
    const int lane = threadIdx.x;
    const int base = b * NPART * 5;   // 40 candidates

    // Two candidate slots per lane (lanes 0..7 hold a second one)
    float v0 = -FLT_MAX, v1 = -FLT_MAX;
    int   i0 = 0x7FFFFFFF, i1 = 0x7FFFFFFF;
    v0 = g_part_val[base + lane];        i0 = g_part_idx[base + lane];
    if (lane < 8) { v1 = g_part_val[base + 32 + lane]; i1 = g_part_idx[base + 32 + lane]; }

    int win_bi[5], win_sel[5];
    float win_v[5];

#pragma unroll
    for (int r = 0; r < 5; r++) {
        // lane-local best of (v0,i0),(v1,i1)
        float mv; int mi; int which;
        if (better(v0, i0, v1, i1)) { mv = v0; mi = i0; which = 0; }
        else                        { mv = v1; mi = i1; which = 1; }
        // warp argmax with tiebreak
        float bv = mv; int bi = mi;
#pragma unroll
        for (int s = 16; s > 0; s >>= 1) {
            float ov = __shfl_xor_sync(0xFFFFFFFF, bv, s);
            int   oi = __shfl_xor_sync(0xFFFFFFFF, bi, s);
            if (better(ov, oi, bv, bi)) { bv = ov; bi = oi; }
        }
        // consume winner (exactly one slot matches the winning index)
        if (mi == bi && mv == bv) {
            if (which == 0) { v0 = -FLT_MAX; i0 = 0x7FFFFFFF; }
            else            { v1 = -FLT_MAX; i1 = 0x7FFFFFFF; }
        }
        win_v[r]   = bv;
        win_bi[r]  = bi / VV;
        win_sel[r] = bi - win_bi[r] * VV;
    }

    if (lane < 5) {
        g_beam_ix[b * KK + lane]  = win_bi[lane];
        out[OFF_SUM + b * KK + lane] = win_v[lane];
    }

    // beam_seq_new: 5 rows of 13 values (12 gathered + selected token)
    for (int idx = lane; idx < 5 * (TT + 1); idx += 32) {
        int j = idx / (TT + 1);
        int t = idx - j * (TT + 1);
        float val;
        if (t < TT) val = (float)beam_seq[(size_t)(b * KK + win_bi[j]) * TT + t];
        else        val = (float)win_sel[j];
        out[OFF_SEQ + (size_t)(b * KK + j) * (TT + 1) + t] = val;
    }
}

// ---------------------------------------------------------------------------
// Kernel 3: fused big gather (bslp rows, float4-vectorized) + state gather.
// grid (50, 2080 + 320), 256 thr.
// ---------------------------------------------------------------------------
__global__ __launch_bounds__(256) void gather_big_kernel(
    const float* __restrict__ bslp,    // (32,5,12,V)
    const float* __restrict__ unaug,   // (160,V)
    const float* __restrict__ state,   // (2,160,512)
    float* __restrict__ out)
{
    const int row = blockIdx.y;

    if (row < NROWS_BSLP) {
        // ---- beam_seq_logprobs_new row copy ----
        const int t   = row % (TT + 1);
        const int bk  = row / (TT + 1);
        const int b   = bk / KK;
        const int bi  = g_beam_ix[bk];

        const float* src;
        if (t < TT) src = bslp + (((size_t)(b * KK + bi) * TT + t) * VV);
        else        src = unaug + (size_t)(b * KK + bi) * VV;

        const size_t dst_off = OFF_BSLP + (size_t)row * VV;
        float* dst = out + dst_off;

        const int a    = (int)(dst_off & 3);
        const int lead = (4 - a) & 3;
        const int nvec = (VV - lead) >> 2;      // float4 count
        const int tail_start = lead + (nvec << 2);

        const int tvec = blockIdx.x * 256 + threadIdx.x;
        if (tvec < nvec) {
            const int v = lead + (tvec << 2);
            float4 val;
            // fast path: src also 16B-aligned at this offset
            if ((((size_t)(src + v)) & 15) == 0) {
                val = *reinterpret_cast<const float4*>(src + v);
            } else {
                val.x = __ldg(src + v + 0);
                val.y = __ldg(src + v + 1);
                val.z = __ldg(src + v + 2);
                val.w = __ldg(src + v + 3);
            }
            *reinterpret_cast<float4*>(dst + v) = val;
        }
        // lead + tail scalars (block 0 only)
        if (blockIdx.x == 0 && threadIdx.x < 8) {
            if (threadIdx.x < 4) {
                int v = threadIdx.x;
                if (v < lead) dst[v] = src[v];
            } else {
                int v = tail_start + (threadIdx.x - 4);
                if (v < VV) dst[v] = src[v];
            }
        }
    } else {
        // ---- state_new row copy (512 floats, both sides 16B-aligned) ----
        if (blockIdx.x != 0) return;
        const int r2 = row - NROWS_BSLP;      // 0..319
        const int s  = r2 / NBEAMS;
        const int j  = r2 - s * NBEAMS;       // b*K + k
        const int b  = j / KK;
        const int bi = g_beam_ix[j];

        const float4* src = reinterpret_cast<const float4*>(
            state + (size_t)s * NBEAMS * HH + (size_t)(b * KK + bi) * HH);
        float4* dst = reinterpret_cast<float4*>(
            out + OFF_STATE + (size_t)r2 * HH);
        if (threadIdx.x < HH / 4)             // 128 float4s
            dst[threadIdx.x] = src[threadIdx.x];
    }
}

// ---------------------------------------------------------------------------
extern "C" void kernel_launch(void* const* d_in, const int* in_sizes, int n_in,
                              void* d_out, int out_size) {
    const float* logprobs = (const float*)d_in[0];       // (160, V)
    const float* unaug    = (const float*)d_in[1];       // (160, V)
    const int*   beam_seq = (const int*)d_in[2];         // (32,5,12) int32
    const float* bslp     = (const float*)d_in[3];       // (32,5,12,V)
    const float* bsum     = (const float*)d_in[4];       // (32,5)
    const float* state    = (const float*)d_in[5];       // (2,160,512)
    // d_in[6] = bdash (=5), hardcoded

    float* out = (float*)d_out;

    {
        dim3 grid(NPART, BB);
        topk_partial_kernel<<<grid, 256>>>(logprobs, bsum);
    }
    topk_merge_kernel<<<BB, 32>>>(beam_seq, out);
    {
        // nvec <= 12564 -> 50 blocks of 256 cover it
        dim3 grid(50, NROWS_BSLP + NROWS_STATE);
        gather_big_kernel<<<grid, 256>>>(bslp, unaug, state, out);
    }
}

// round 6
// speedup vs baseline: 1.4504x; 1.3054x over previous
#include <cuda_runtime.h>
#include <cstdint>
#include <cfloat>

// Problem constants
#define BB 32
#define KK 5
#define TT 12
#define VV 50257
#define HH 512
#define NBEAMS (BB*KK)           // 160
#define NPART 32                 // v-partitions per batch row
#define PERV ((VV + NPART - 1) / NPART)   // 1571

// Output layout: ONE f32 buffer, outputs cast to f32, concatenated in
// reference return order (element offsets). Verified: rel_err == 0.
#define OFF_SEQ   ((size_t)0)                         // 32*5*13 = 2080
#define OFF_BSLP  ((size_t)2080)
#define OFF_SUM   (OFF_BSLP + (size_t)BB*KK*13*VV)    // 104536640
#define OFF_STATE (OFF_SUM + (size_t)NBEAMS)          // 104536800 (mod 4 == 0)

#define NROWS_BSLP (BB*KK*(TT+1))   // 2080
#define NROWS_STATE (2*NBEAMS)      // 320

// Scratch (static device globals; no allocation)
__device__ float g_part_val[BB * NPART * 5];
__device__ int   g_part_idx[BB * NPART * 5];
__device__ int   g_beam_ix[NBEAMS];

__device__ __forceinline__ bool better(float va, int ia, float vb, int ib) {
    return (va > vb) || (va == vb && ia < ib);
}

// ---------------------------------------------------------------------------
// Kernel 1: partial top-5 per (batch row, v-partition). grid (NPART, BB).
// v-outer / k-inner: 5 independent coalesced loads per iteration (MLP=5).
// ---------------------------------------------------------------------------
__global__ __launch_bounds__(256) void topk_partial_kernel(
    const float* __restrict__ logprobs,   // (160, V)
    const float* __restrict__ bsum)       // (32, 5)
{
    const int b       = blockIdx.y;
    const int part    = blockIdx.x;
    const int v_start = part * PERV;
    const int v_end   = min(v_start + PERV, VV);
    const int tid     = threadIdx.x;

    float bs[KK];
#pragma unroll
    for (int k = 0; k < KK; k++) bs[k] = bsum[b * KK + k];

    float tv[5]; int ti[5];
#pragma unroll
    for (int j = 0; j < 5; j++) { tv[j] = -FLT_MAX; ti[j] = 0x7FFFFFFF; }

    const float* lpb = logprobs + (size_t)b * KK * VV;
    for (int v = v_start + tid; v < v_end; v += 256) {
        float x[KK];
#pragma unroll
        for (int k = 0; k < KK; k++) x[k] = __ldg(lpb + (size_t)k * VV + v);
#pragma unroll
        for (int k = 0; k < KK; k++) {
            float val = bs[k] + x[k];
            int   idx = k * VV + v;
            if (better(val, idx, tv[4], ti[4])) {
                tv[4] = val; ti[4] = idx;
#pragma unroll
                for (int j = 4; j > 0; j--) {
                    if (better(tv[j], ti[j], tv[j-1], ti[j-1])) {
                        float fv = tv[j]; tv[j] = tv[j-1]; tv[j-1] = fv;
                        int   iv = ti[j]; ti[j] = ti[j-1]; ti[j-1] = iv;
                    }
                }
            }
        }
    }

    __shared__ float sv[256 * 5];
    __shared__ int   si[256 * 5];
#pragma unroll
    for (int j = 0; j < 5; j++) { sv[tid*5+j] = tv[j]; si[tid*5+j] = ti[j]; }
    __syncthreads();

    for (int s = 128; s > 0; s >>= 1) {
        if (tid < s) {
            // merge sorted 5-lists at tid and tid+s -> tid
            float mv[5]; int mi[5];
            int pa = 0, pb = 0;
            const int A = tid * 5, Bo = (tid + s) * 5;
#pragma unroll
            for (int j = 0; j < 5; j++) {
                if (better(sv[A+pa], si[A+pa], sv[Bo+pb], si[Bo+pb])) {
                    mv[j] = sv[A+pa]; mi[j] = si[A+pa]; pa++;
                } else {
                    mv[j] = sv[Bo+pb]; mi[j] = si[Bo+pb]; pb++;
                }
            }
#pragma unroll
            for (int j = 0; j < 5; j++) { sv[A+j] = mv[j]; si[A+j] = mi[j]; }
        }
        __syncthreads();
    }

    if (tid == 0) {
        const int base = (b * NPART + part) * 5;
#pragma unroll
        for (int j = 0; j < 5; j++) {
            g_part_val[base + j] = sv[j];
            g_part_idx[base + j] = si[j];
        }
    }
}

// ---------------------------------------------------------------------------
// Kernel 2: warp-parallel merge of 32 sorted 5-lists per batch row.
// grid (BB), 32 threads. Each lane owns one sorted partial list held in a
// shift register (static indexing). 5 rounds of warp argmax with tiebreak.
// ---------------------------------------------------------------------------
__global__ __launch_bounds__(32) void topk_merge_kernel(
    const int* __restrict__ beam_seq,  // (32,5,12) int32
    float* __restrict__ out)
{
    const int b    = blockIdx.x;
    const int lane = threadIdx.x;
    const int base = (b * NPART + lane) * 5;

    // Lane-local sorted list (descending) in a shift register
    float v0 = g_part_val[base+0], v1 = g_part_val[base+1], v2 = g_part_val[base+2],
          v3 = g_part_val[base+3], v4 = g_part_val[base+4];
    int   i0 = g_part_idx[base+0], i1 = g_part_idx[base+1], i2 = g_part_idx[base+2],
          i3 = g_part_idx[base+3], i4 = g_part_idx[base+4];

    int win_bi[5], win_sel[5];
    float win_v[5];

#pragma unroll
    for (int r = 0; r < 5; r++) {
        float bv = v0; int bi = i0;
#pragma unroll
        for (int s = 16; s > 0; s >>= 1) {
            float ov = __shfl_xor_sync(0xFFFFFFFF, bv, s);
            int   oi = __shfl_xor_sync(0xFFFFFFFF, bi, s);
            if (better(ov, oi, bv, bi)) { bv = ov; bi = oi; }
        }
        // winner lane consumes its head (flat indices are unique)
        if (i0 == bi) {
            v0 = v1; i0 = i1; v1 = v2; i1 = i2;
            v2 = v3; i2 = i3; v3 = v4; i3 = i4;
            v4 = -FLT_MAX; i4 = 0x7FFFFFFF;
        }
        win_v[r]   = bv;
        win_bi[r]  = bi / VV;
        win_sel[r] = bi - win_bi[r] * VV;
    }

    if (lane < 5) {
        g_beam_ix[b * KK + lane]     = win_bi[lane];
        out[OFF_SUM + b * KK + lane] = win_v[lane];
    }

    // beam_seq_new: 5 rows of 13 values (12 gathered + selected token)
    for (int idx = lane; idx < 5 * (TT + 1); idx += 32) {
        int j = idx / (TT + 1);
        int t = idx - j * (TT + 1);
        float val;
        if (t < TT) val = (float)beam_seq[(size_t)(b * KK + win_bi[j]) * TT + t];
        else        val = (float)win_sel[j];
        out[OFF_SEQ + (size_t)(b * KK + j) * (TT + 1) + t] = val;
    }
}

// ---------------------------------------------------------------------------
// Kernel 3: fused big gather (bslp rows, float4-vectorized) + state gather.
// grid (50, 2080 + 320), 256 thr. At HBM roofline (~7.9 TB/s measured).
// ---------------------------------------------------------------------------
__global__ __launch_bounds__(256) void gather_big_kernel(
    const float* __restrict__ bslp,    // (32,5,12,V)
    const float* __restrict__ unaug,   // (160,V)
    const float* __restrict__ state,   // (2,160,512)
    float* __restrict__ out)
{
    const int row = blockIdx.y;

    if (row < NROWS_BSLP) {
        // ---- beam_seq_logprobs_new row copy ----
        const int t   = row % (TT + 1);
        const int bk  = row / (TT + 1);
        const int b   = bk / KK;
        const int bi  = g_beam_ix[bk];

        const float* src;
        if (t < TT) src = bslp + (((size_t)(b * KK + bi) * TT + t) * VV);
        else        src = unaug + (size_t)(b * KK + bi) * VV;

        const size_t dst_off = OFF_BSLP + (size_t)row * VV;
        float* dst = out + dst_off;

        const int a    = (int)(dst_off & 3);
        const int lead = (4 - a) & 3;
        const int nvec = (VV - lead) >> 2;      // float4 count
        const int tail_start = lead + (nvec << 2);

        const int tvec = blockIdx.x * 256 + threadIdx.x;
        if (tvec < nvec) {
            const int v = lead + (tvec << 2);
            float4 val;
            if ((((size_t)(src + v)) & 15) == 0) {
                val = *reinterpret_cast<const float4*>(src + v);
            } else {
                val.x = __ldg(src + v + 0);
                val.y = __ldg(src + v + 1);
                val.z = __ldg(src + v + 2);
                val.w = __ldg(src + v + 3);
            }
            *reinterpret_cast<float4*>(dst + v) = val;
        }
        if (blockIdx.x == 0 && threadIdx.x < 8) {
            if (threadIdx.x < 4) {
                int v = threadIdx.x;
                if (v < lead) dst[v] = src[v];
            } else {
                int v = tail_start + (threadIdx.x - 4);
                if (v < VV) dst[v] = src[v];
            }
        }
    } else {
        // ---- state_new row copy (512 floats, both sides 16B-aligned) ----
        if (blockIdx.x != 0) return;
        const int r2 = row - NROWS_BSLP;      // 0..319
        const int s  = r2 / NBEAMS;
        const int j  = r2 - s * NBEAMS;       // b*K + k
        const int b  = j / KK;
        const int bi = g_beam_ix[j];

        const float4* src = reinterpret_cast<const float4*>(
            state + (size_t)s * NBEAMS * HH + (size_t)(b * KK + bi) * HH);
        float4* dst = reinterpret_cast<float4*>(
            out + OFF_STATE + (size_t)r2 * HH);
        if (threadIdx.x < HH / 4)             // 128 float4s
            dst[threadIdx.x] = src[threadIdx.x];
    }
}

// ---------------------------------------------------------------------------
extern "C" void kernel_launch(void* const* d_in, const int* in_sizes, int n_in,
                              void* d_out, int out_size) {
    const float* logprobs = (const float*)d_in[0];       // (160, V)
    const float* unaug    = (const float*)d_in[1];       // (160, V)
    const int*   beam_seq = (const int*)d_in[2];         // (32,5,12) int32
    const float* bslp     = (const float*)d_in[3];       // (32,5,12,V)
    const float* bsum     = (const float*)d_in[4];       // (32,5)
    const float* state    = (const float*)d_in[5];       // (2,160,512)
    // d_in[6] = bdash (=5), hardcoded

    float* out = (float*)d_out;

    {
        dim3 grid(NPART, BB);   // (32, 32) = 1024 blocks
        topk_partial_kernel<<<grid, 256>>>(logprobs, bsum);
    }
    topk_merge_kernel<<<BB, 32>>>(beam_seq, out);
    {
        dim3 grid(50, NROWS_BSLP + NROWS_STATE);
        gather_big_kernel<<<grid, 256>>>(bslp, unaug, state, out);
    }
}